// round 5
// baseline (speedup 1.0000x reference)
#include <cuda_runtime.h>

__device__ int g_adj_is_i64;   // 1 if adjacency buffer is int64-LE, else int32

__global__ void detect_adj_kernel(const unsigned int* __restrict__ adj_words) {
    // int64-LE indices < 2^31 => odd words of first 32 "elements" are all 0.
    // Probe stays within first 256 bytes: in-bounds for both layouts.
    int all_zero = 1;
    for (int k = 1; k < 64; k += 2)
        if (adj_words[k] != 0u) { all_zero = 0; break; }
    g_adj_is_i64 = all_zero;
}

__global__ void zero_out_kernel(float* __restrict__ out, int n) {
    int i = blockIdx.x * blockDim.x + threadIdx.x;
    if (i < n) out[i] = 0.0f;
}

__device__ __forceinline__ float fast_sigmoid(float x) {
    // sigmoid(x) = 0.5 * tanh(0.5x) + 0.5 ; tanh.approx.f32 is 1 MUFU op
    float t;
    asm("tanh.approx.f32 %0, %1;" : "=f"(t) : "f"(x * 0.5f));
    return fmaf(t, 0.5f, 0.5f);
}

__global__ __launch_bounds__(256) void mesh_mlp_kernel(
    const float* __restrict__ points,        // [N_POINTS, 2]
    const void*  __restrict__ adj_raw,       // [N_ELEMS, 3] int32 or int64
    const float* __restrict__ W1, const float* __restrict__ b1,
    const float* __restrict__ W2, const float* __restrict__ b2,
    const float* __restrict__ W3, const float* __restrict__ b3,
    const float* __restrict__ W4, const float* __restrict__ b4,
    float* __restrict__ out,                 // [N_POINTS]
    int n_elems, int n_points)
{
    __shared__ float sW1[48], sb1[8];
    __shared__ float sW2[64], sb2[8];
    __shared__ float sW3[64], sb3[8];
    __shared__ float sW4[24], sb4[3];

    int t = threadIdx.x;
    if (t < 48) sW1[t] = W1[t];
    if (t < 8)  sb1[t] = b1[t];
    if (t < 64) sW2[t] = W2[t];
    if (t >= 64 && t < 72) sb2[t - 64] = b2[t - 64];
    if (t >= 128 && t < 192) sW3[t - 128] = W3[t - 128];
    if (t >= 192 && t < 200) sb3[t - 192] = b3[t - 192];
    if (t >= 200 && t < 224) sW4[t - 200] = W4[t - 200];
    if (t >= 224 && t < 227) sb4[t - 224] = b4[t - 224];
    __syncthreads();

    int e = blockIdx.x * blockDim.x + t;
    if (e >= n_elems) return;

    long long base = (long long)e * 3;
    int i0, i1, i2;
    if (g_adj_is_i64) {                      // uniform branch
        const long long* a = (const long long*)adj_raw;
        i0 = (int)a[base + 0];
        i1 = (int)a[base + 1];
        i2 = (int)a[base + 2];
    } else {
        const int* a = (const int*)adj_raw;
        i0 = a[base + 0];
        i1 = a[base + 1];
        i2 = a[base + 2];
    }
    // insurance: convert any surprise into rel_err, not a device trap
    i0 = min(max(i0, 0), n_points - 1);
    i1 = min(max(i1, 0), n_points - 1);
    i2 = min(max(i2, 0), n_points - 1);

    const float2* pts2 = (const float2*)points;
    float2 p0 = pts2[i0];
    float2 p1 = pts2[i1];
    float2 p2 = pts2[i2];

    float x[6] = {p0.x, p0.y, p1.x, p1.y, p2.x, p2.y};

    float h1[8];
#pragma unroll
    for (int j = 0; j < 8; ++j) {
        float acc = sb1[j];
#pragma unroll
        for (int i = 0; i < 6; ++i) acc = fmaf(x[i], sW1[i * 8 + j], acc);
        h1[j] = fast_sigmoid(acc);
    }

    float h2[8];
#pragma unroll
    for (int j = 0; j < 8; ++j) {
        float acc = sb2[j];
#pragma unroll
        for (int i = 0; i < 8; ++i) acc = fmaf(h1[i], sW2[i * 8 + j], acc);
        h2[j] = fast_sigmoid(acc);
    }

    float h3[8];
#pragma unroll
    for (int j = 0; j < 8; ++j) {
        float acc = sb3[j];
#pragma unroll
        for (int i = 0; i < 8; ++i) acc = fmaf(h2[i], sW3[i * 8 + j], acc);
        h3[j] = fast_sigmoid(acc);
    }

    float o[3];
#pragma unroll
    for (int j = 0; j < 3; ++j) {
        float acc = sb4[j];
#pragma unroll
        for (int i = 0; i < 8; ++i) acc = fmaf(h3[i], sW4[i * 3 + j], acc);
        o[j] = fast_sigmoid(acc);
    }

    atomicAdd(&out[i0], o[0]);
    atomicAdd(&out[i1], o[1]);
    atomicAdd(&out[i2], o[2]);
}

extern "C" void kernel_launch(void* const* d_in, const int* in_sizes, int n_in,
                              void* d_out, int out_size) {
    // Resolve inputs by SIZE, not by position (robust to metadata ordering).
    //   adjacency : 12,000,000 elements (int32 or int64 — detected on device)
    //   points    : 4,000,000 float32
    //   W1: 48, W2: 64, W3: 64, W4: 24, b1/b2/b3: 8, b4: 3
    const float* points = nullptr;
    const void*  adj    = nullptr;
    const float *W1 = nullptr, *b1 = nullptr, *W2 = nullptr, *b2 = nullptr;
    const float *W3 = nullptr, *b3 = nullptr, *W4 = nullptr, *b4 = nullptr;
    int n_points = 0, n_elems = 0;

    int n8_seen = 0;   // b1, b2, b3 in encounter order
    int n64_seen = 0;  // W2, W3 in encounter order

    for (int i = 0; i < n_in; ++i) {
        int sz = in_sizes[i];
        const void* p = d_in[i];
        if (sz >= 6000000) {            // adjacency (12M)
            adj = p; n_elems = sz / 3;
        } else if (sz >= 1000000) {     // points (4M floats)
            points = (const float*)p; n_points = sz / 2;
        } else if (sz == 48) {
            W1 = (const float*)p;
        } else if (sz == 64) {
            if (n64_seen++ == 0) W2 = (const float*)p; else W3 = (const float*)p;
        } else if (sz == 24) {
            W4 = (const float*)p;
        } else if (sz == 8) {
            if (n8_seen == 0) b1 = (const float*)p;
            else if (n8_seen == 1) b2 = (const float*)p;
            else b3 = (const float*)p;
            n8_seen++;
        } else if (sz == 3) {
            b4 = (const float*)p;
        }
    }

    float* out = (float*)d_out;

    detect_adj_kernel<<<1, 1>>>((const unsigned int*)adj);
    zero_out_kernel<<<(out_size + 255) / 256, 256>>>(out, out_size);
    mesh_mlp_kernel<<<(n_elems + 255) / 256, 256>>>(
        points, adj, W1, b1, W2, b2, W3, b3, W4, b4, out, n_elems, n_points);
}